// round 2
// baseline (speedup 1.0000x reference)
#include <cuda_runtime.h>

// out[b] = expm( 0.5*(omega[e] - omega[e]^T) ) @ J[b],  e = edge_indices[b]
// Computed as Taylor series applied directly to the vector (never form U).
// K = 8, skew-symmetric A kept as 28 upper-triangle registers.
//
// NOTE: JAX default config downgrades int64 -> int32, so edge_indices is int32.

constexpr int K = 8;
constexpr int NTERMS = 6;   // remainder ~ ||A||^7/7! << 1e-6, threshold 1e-3

__device__ __host__ constexpr int tri(int i, int j) {  // i < j, upper triangle index
    return i * K - (i * (i + 1)) / 2 + (j - i - 1);    // 0..27
}

__global__ void __launch_bounds__(256)
gauge_transport_kernel(const float* __restrict__ omega,  // (E,8,8)
                       const float* __restrict__ Jv,     // (B,8)
                       const int*   __restrict__ eidx,   // (B,) int32 (JAX x64-off)
                       float* __restrict__ out,          // (B,8)
                       int B)
{
    int b = blockIdx.x * blockDim.x + threadIdx.x;
    if (b >= B) return;

    unsigned int e = (unsigned int)eidx[b];

    // Gather one 256B omega tile (16 x float4) — front-batched for MLP.
    const float4* wp = reinterpret_cast<const float4*>(omega + (size_t)e * (K * K));
    float w[K * K];
    #pragma unroll
    for (int q = 0; q < 16; q++) {
        float4 v = __ldg(wp + q);
        w[4 * q + 0] = v.x;
        w[4 * q + 1] = v.y;
        w[4 * q + 2] = v.z;
        w[4 * q + 3] = v.w;
    }

    // Skew-symmetrize: a[i][j] = 0.5*(w[i][j] - w[j][i]), keep upper triangle.
    float a[28];
    #pragma unroll
    for (int i = 0; i < K; i++)
        #pragma unroll
        for (int j = i + 1; j < K; j++)
            a[tri(i, j)] = 0.5f * (w[i * K + j] - w[j * K + i]);

    // Load J[b] (two coalesced float4).
    const float4* jp = reinterpret_cast<const float4*>(Jv + (size_t)b * K);
    float4 j0 = __ldg(jp + 0);
    float4 j1 = __ldg(jp + 1);

    float t[K]   = { j0.x, j0.y, j0.z, j0.w, j1.x, j1.y, j1.z, j1.w };
    float acc[K] = { j0.x, j0.y, j0.z, j0.w, j1.x, j1.y, j1.z, j1.w };

    // acc = sum_{n=0..NTERMS} A^n v / n!
    #pragma unroll
    for (int n = 1; n <= NTERMS; n++) {
        const float inv = 1.0f / (float)n;   // compile-time constant per unrolled iter
        float nt[K];
        #pragma unroll
        for (int i = 0; i < K; i++) {
            float s = 0.0f;
            #pragma unroll
            for (int j = 0; j < K; j++) {
                if (j > i)      s = fmaf( a[tri(i, j)], t[j], s);
                else if (j < i) s = fmaf(-a[tri(j, i)], t[j], s);
            }
            nt[i] = s * inv;
        }
        #pragma unroll
        for (int i = 0; i < K; i++) {
            t[i] = nt[i];
            acc[i] += t[i];
        }
    }

    float4* op = reinterpret_cast<float4*>(out + (size_t)b * K);
    op[0] = make_float4(acc[0], acc[1], acc[2], acc[3]);
    op[1] = make_float4(acc[4], acc[5], acc[6], acc[7]);
}

extern "C" void kernel_launch(void* const* d_in, const int* in_sizes, int n_in,
                              void* d_out, int out_size)
{
    const float* omega = (const float*)d_in[0];  // (E,8,8) fp32
    const float* Jv    = (const float*)d_in[1];  // (B,8)   fp32
    const int*   eidx  = (const int*)d_in[2];    // (B,)    int32
    // d_in[3] = edges (E,2) — unused by the reference output.

    float* out = (float*)d_out;
    int B = in_sizes[2];  // number of transport events

    int threads = 256;
    int blocks  = (B + threads - 1) / threads;
    gauge_transport_kernel<<<blocks, threads>>>(omega, Jv, eidx, out, B);
}